// round 4
// baseline (speedup 1.0000x reference)
#include <cuda_runtime.h>
#include <math.h>

// Dims
#define BB 16
#define NCO 64
#define NT 16
#define NHW 1024

// ---------------- persistent scratch (device globals; no allocation) -------
__device__ float g_h [BB*NCO*NHW];     // attended h (recurrent carry)   4 MB
__device__ float g_hg[BB*NCO*NHW];     // pre-attention h (gate output)  4 MB
__device__ float g_c [BB*NCO*NHW];     // cell state                     4 MB
__device__ float g_q [BB*16*NHW];      //  1 MB
__device__ float g_k [BB*16*NHW];      //  1 MB
__device__ float g_v [BB*NCO*NHW];     //  4 MB

// ---------------- init: zero h and c ---------------------------------------
__global__ void k_init()
{
    int i = blockIdx.x * 256 + threadIdx.x;
    g_h[i] = 0.f;
    g_c[i] = 0.f;
}

__device__ __forceinline__ float sigf(float x) { return 1.f / (1.f + __expf(-x)); }
__device__ __forceinline__ float tanh_fast(float x)
{
    return __fdividef(2.f, 1.f + __expf(-2.f * x)) - 1.f;
}

// ---------------- conv 3x3 + ConvLSTM gating fused -------------------------
// grid (16 chan-groups of 4, 16 batch), 256 threads.
__global__ void __launch_bounds__(256, 2) k_convgate(
    const float* __restrict__ X,   const float* __restrict__ Wc,
    const float* __restrict__ bc,
    const float* __restrict__ Wci, const float* __restrict__ Wcf,
    const float* __restrict__ Wco, int t)
{
    __shared__ float in_s[4 * 34 * 37];   // 4 ci, 34 rows, stride 37 (20.1 KB)
    __shared__ float w_s[16 * 36];        // 16 co x 4 ci x 9           (2.3 KB)

    const int b   = blockIdx.y;
    const int ch0 = blockIdx.x * 4;
    const int tid = threadIdx.x;
    const int y   = tid >> 3;            // 0..31
    const int x4  = (tid & 7) << 2;      // 0,4,...,28

    float acc[16][4];
    #pragma unroll
    for (int j = 0; j < 16; ++j)
        #pragma unroll
        for (int p = 0; p < 4; ++p) acc[j][p] = 0.f;

    for (int ch = 0; ch < 32; ++ch) {            // 32 chunks of 4 input ch.
        for (int i = tid; i < 576; i += 256) {
            int j = i / 36; int r = i - j * 36;
            int cog = ((j >> 2) << 6) + ch0 + (j & 3);
            w_s[i] = Wc[(cog * 128 + (ch * 4 + r / 9)) * 9 + (r % 9)];
        }
        for (int i = tid; i < 4 * 1156; i += 256) {
            int cc = i / 1156; int r = i - cc * 1156;
            int yy = r / 34;   int xx = r - yy * 34;
            int iy = yy - 1,   ix = xx - 1;
            int ci = ch * 4 + cc;
            const float* src = (ci < 64)
                ? (X + ((b * 64 + ci) * 16 + t) * 1024)
                : (g_h + (b * 64 + (ci - 64)) * 1024);
            float v = 0.f;
            if (iy >= 0 && iy < 32 && ix >= 0 && ix < 32) v = src[iy * 32 + ix];
            in_s[cc * 1258 + yy * 37 + xx] = v;
        }
        __syncthreads();

        #pragma unroll
        for (int cc = 0; cc < 4; ++cc) {
            float v[3][6];
            #pragma unroll
            for (int dy = 0; dy < 3; ++dy)
                #pragma unroll
                for (int dx = 0; dx < 6; ++dx)
                    v[dy][dx] = in_s[cc * 1258 + (y + dy) * 37 + (x4 + dx)];
            #pragma unroll
            for (int j = 0; j < 16; ++j) {
                const float* wp = &w_s[j * 36 + cc * 9];
                float w0 = wp[0], w1 = wp[1], w2 = wp[2];
                float w3 = wp[3], w4 = wp[4], w5 = wp[5];
                float w6 = wp[6], w7 = wp[7], w8 = wp[8];
                #pragma unroll
                for (int p = 0; p < 4; ++p) {
                    acc[j][p] += w0 * v[0][p] + w1 * v[0][p + 1] + w2 * v[0][p + 2]
                               + w3 * v[1][p] + w4 * v[1][p + 1] + w5 * v[1][p + 2]
                               + w6 * v[2][p] + w7 * v[2][p + 1] + w8 * v[2][p + 2];
                }
            }
        }
        __syncthreads();
    }

    #pragma unroll
    for (int cl = 0; cl < 4; ++cl) {
        int ch = ch0 + cl;
        float bi = bc[ch], bf = bc[64 + ch], bg = bc[128 + ch], bo = bc[192 + ch];
        #pragma unroll
        for (int p = 0; p < 4; ++p) {
            int pos = y * 32 + x4 + p;
            int idx = (b * 64 + ch) * 1024 + pos;
            int wpp = ch * 1024 + pos;
            float cp = g_c[idx];
            float ii = sigf(acc[cl][p]      + bi + Wci[wpp] * cp);
            float ff = sigf(acc[4 + cl][p]  + bf + Wcf[wpp] * cp);
            float nc = ff * cp + ii * tanh_fast(acc[8 + cl][p] + bg);
            float oo = sigf(acc[12 + cl][p] + bo + Wco[wpp] * nc);
            g_c[idx]  = nc;
            g_hg[idx] = oo * tanh_fast(nc);
        }
    }
}

// ---------------- q,k,v 1x1 convs: 96 output ch from 64 --------------------
__global__ void k_qkv(const float* __restrict__ qw, const float* __restrict__ qb,
                      const float* __restrict__ kw, const float* __restrict__ kb,
                      const float* __restrict__ vw, const float* __restrict__ vb)
{
    __shared__ float h_s[32 * 256];
    __shared__ float w_s[8 * 64];

    const int p0  = blockIdx.x * 256;
    const int oc0 = blockIdx.y * 8;
    const int b   = blockIdx.z;
    const int tid = threadIdx.x;

    for (int i = tid; i < 512; i += 256) {
        int j = i >> 6; int c = i & 63; int oc = oc0 + j;
        w_s[i] = (oc < 16) ? qw[oc * 64 + c]
               : (oc < 32) ? kw[(oc - 16) * 64 + c]
                           : vw[(oc - 32) * 64 + c];
    }

    float acc[8];
    #pragma unroll
    for (int j = 0; j < 8; ++j) {
        int oc = oc0 + j;
        acc[j] = (oc < 16) ? qb[oc] : (oc < 32) ? kb[oc - 16] : vb[oc - 32];
    }

    for (int chh = 0; chh < 2; ++chh) {
        __syncthreads();
        for (int i = tid; i < 8192; i += 256) {
            int c = i >> 8; int j = i & 255;
            h_s[i] = g_hg[(b * 64 + chh * 32 + c) * 1024 + p0 + j];
        }
        __syncthreads();
        #pragma unroll 8
        for (int c = 0; c < 32; ++c) {
            float hv = h_s[c * 256 + tid];
            #pragma unroll
            for (int j = 0; j < 8; ++j)
                acc[j] += w_s[j * 64 + chh * 32 + c] * hv;
        }
    }

    int pos = p0 + tid;
    #pragma unroll
    for (int j = 0; j < 8; ++j) {
        int oc = oc0 + j;
        if (oc < 16)      g_q[(b * 16 + oc) * 1024 + pos]        = acc[j];
        else if (oc < 32) g_k[(b * 16 + (oc - 16)) * 1024 + pos] = acc[j];
        else              g_v[(b * 64 + (oc - 32)) * 1024 + pos] = acc[j];
    }
}

// ---------------- fused attention: scores+softmax+P@v^T+z_w+write ----------
// grid (64 row-groups of 16, 16 batch), 256 threads = 8 warps.
// Phases A/B: warp = 2 rows, full score row register-resident.
// Phase C: P transposed into smem per 128-m chunk; GEMM in outer-product
// orientation (thread = 1 channel x 4 rows) -> no cross-lane reductions.
__global__ void __launch_bounds__(256, 2) k_attn(
    const float* __restrict__ zw, const float* __restrict__ zb,
    float* __restrict__ out, int t)
{
    __shared__ float smem[12288];            // 48 KB exactly
    float* z_s = smem;                       // [64][20] = 1280, persists C->D
    float* u_s = smem + 1280;                // 11008-float staging union
    float* P_s = u_s;                        // phase C: [128][20] = 2560
    float* v_s = u_s + 2560;                 // phase C: [64][132] = 8448

    const int b    = blockIdx.y;
    const int n0b  = blockIdx.x * 16;
    const int tid  = threadIdx.x;
    const int w    = tid >> 5;
    const int lane = tid & 31;
    const int rl   = w * 2;                  // this warp's first local row
    const int r0   = n0b + rl;

    // ---- phase A: scores s[32] per row (q . k), k staged 256-m at a time --
    float q0[16], q1[16];
    #pragma unroll
    for (int c = 0; c < 16; ++c) {
        q0[c] = g_q[(b * 16 + c) * 1024 + r0];
        q1[c] = g_q[(b * 16 + c) * 1024 + r0 + 1];
    }

    float s0[32], s1[32];
    for (int chh = 0; chh < 4; ++chh) {
        __syncthreads();
        for (int i = tid; i < 4096; i += 256) {
            int c = i >> 8; int mm = i & 255;
            u_s[i] = g_k[(b * 16 + c) * 1024 + chh * 256 + mm];
        }
        __syncthreads();
        #pragma unroll
        for (int jj = 0; jj < 8; ++jj) {
            int j  = chh * 8 + jj;
            int mm = jj * 32 + lane;
            float a = 0.f, bb2 = 0.f;
            #pragma unroll
            for (int c = 0; c < 16; ++c) {
                float kv = u_s[c * 256 + mm];
                a   += q0[c] * kv;
                bb2 += q1[c] * kv;
            }
            s0[j] = a; s1[j] = bb2;
        }
    }

    // ---- phase B: softmax over m (registers + warp butterflies) ----
    float m0 = -1e30f, m1 = -1e30f;
    #pragma unroll
    for (int j = 0; j < 32; ++j) { m0 = fmaxf(m0, s0[j]); m1 = fmaxf(m1, s1[j]); }
    #pragma unroll
    for (int o = 16; o > 0; o >>= 1) {
        m0 = fmaxf(m0, __shfl_xor_sync(0xffffffffu, m0, o));
        m1 = fmaxf(m1, __shfl_xor_sync(0xffffffffu, m1, o));
    }
    float sum0 = 0.f, sum1 = 0.f;
    #pragma unroll
    for (int j = 0; j < 32; ++j) {
        s0[j] = __expf(s0[j] - m0); sum0 += s0[j];
        s1[j] = __expf(s1[j] - m1); sum1 += s1[j];
    }
    #pragma unroll
    for (int o = 16; o > 0; o >>= 1) {
        sum0 += __shfl_xor_sync(0xffffffffu, sum0, o);
        sum1 += __shfl_xor_sync(0xffffffffu, sum1, o);
    }
    float inv0 = 1.f / sum0, inv1 = 1.f / sum1;
    #pragma unroll
    for (int j = 0; j < 32; ++j) { s0[j] *= inv0; s1[j] *= inv1; }

    // ---- phase C: z[c][row] = sum_m P[row][m] v[c][m], 128-m chunks ----
    // Thread owns channel cth and rows ng0..ng0+3.
    const int cth = tid >> 2;                // 0..63
    const int ng0 = (tid & 3) << 2;          // 0,4,8,12
    float zacc[4] = {0.f, 0.f, 0.f, 0.f};

    for (int cm = 0; cm < 8; ++cm) {
        __syncthreads();
        // stage P transposed: P_s[m_local][row], stride 20
        const int chh = cm >> 1, jj0 = (cm & 1) * 4;
        #pragma unroll
        for (int jjl = 0; jjl < 4; ++jjl) {
            int j  = chh * 8 + jj0 + jjl;
            int ml = jjl * 32 + lane;
            P_s[ml * 20 + rl]     = s0[j];
            P_s[ml * 20 + rl + 1] = s1[j];
        }
        // stage v (c-major, natural): v_s[c][m_local], stride 132
        const int mbase = cm * 128;
        #pragma unroll
        for (int r = 0; r < 8; ++r) {
            int q  = tid + r * 256;
            int c  = q >> 5;
            int m4 = (q & 31) << 2;
            float4 vv = *reinterpret_cast<const float4*>(
                &g_v[(b * 64 + c) * 1024 + mbase + m4]);
            *reinterpret_cast<float4*>(&v_s[c * 132 + m4]) = vv;
        }
        __syncthreads();
        // GEMM: per m, 1 broadcast LDS.32 + 1 LDS.128 + 4 FFMA
        #pragma unroll 4
        for (int m = 0; m < 128; ++m) {
            float4 p4 = *reinterpret_cast<const float4*>(&P_s[m * 20 + ng0]);
            float  vv = v_s[cth * 132 + m];
            zacc[0] += vv * p4.x; zacc[1] += vv * p4.y;
            zacc[2] += vv * p4.z; zacc[3] += vv * p4.w;
        }
    }

    __syncthreads();
    *reinterpret_cast<float4*>(&z_s[cth * 20 + ng0]) =
        make_float4(zacc[0], zacc[1], zacc[2], zacc[3]);

    // ---- phase D: attended = z_w @ z + z_b; write out + g_h ----
    for (int i = tid; i < 4096; i += 256) u_s[i] = zw[i];
    __syncthreads();

    const int oc = tid >> 2;
    const int rg = (tid & 3) << 2;
    float a4[4];
    float bv = zb[oc];
    #pragma unroll
    for (int i = 0; i < 4; ++i) a4[i] = bv;
    #pragma unroll 8
    for (int c = 0; c < 64; ++c) {
        float wv = u_s[oc * 64 + c];
        float4 zv = *reinterpret_cast<const float4*>(&z_s[c * 20 + rg]);
        a4[0] += wv * zv.x; a4[1] += wv * zv.y;
        a4[2] += wv * zv.z; a4[3] += wv * zv.w;
    }
    #pragma unroll
    for (int i = 0; i < 4; ++i) {
        int n = n0b + rg + i;
        g_h[(b * 64 + oc) * 1024 + n] = a4[i];
        out[((b * 64 + oc) * 16 + t) * 1024 + n] = a4[i];
    }
}

// ---------------- orchestration --------------------------------------------
extern "C" void kernel_launch(void* const* d_in, const int* in_sizes, int n_in,
                              void* d_out, int out_size)
{
    (void)in_sizes; (void)n_in; (void)out_size;
    const float* X   = (const float*)d_in[0];
    const float* Wc  = (const float*)d_in[1];
    const float* bcc = (const float*)d_in[2];
    const float* Wci = (const float*)d_in[3];
    const float* Wcf = (const float*)d_in[4];
    const float* Wco = (const float*)d_in[5];
    const float* qw  = (const float*)d_in[6];
    const float* qb  = (const float*)d_in[7];
    const float* kw  = (const float*)d_in[8];
    const float* kb  = (const float*)d_in[9];
    const float* vw  = (const float*)d_in[10];
    const float* vb  = (const float*)d_in[11];
    const float* zw  = (const float*)d_in[12];
    const float* zb  = (const float*)d_in[13];
    float* out = (float*)d_out;

    k_init<<<4096, 256>>>();
    for (int t = 0; t < NT; ++t) {
        k_convgate<<<dim3(16, 16),    256>>>(X, Wc, bcc, Wci, Wcf, Wco, t);
        k_qkv     <<<dim3(4, 12, 16), 256>>>(qw, qb, kw, kb, vw, vb);
        k_attn    <<<dim3(64, 16),    256>>>(zw, zb, out, t);
    }
}